// round 14
// baseline (speedup 1.0000x reference)
#include <cuda_runtime.h>
#include <cuda_bf16.h>
#include <stdint.h>
#include <math.h>
#include <stddef.h>

#define BATCH 2048
#define INF   1024
#define OUTF  2048
#define LAMBDA 0.2f
#define ADMM_ITERS 100
#define NEWTON_MMA_ITERS 12
#define NEWTON_F32_ITERS 2
typedef __nv_bfloat16 bf16;

// ---------------- scratch ----------------
__device__ float g_Mf [OUTF * OUTF];
__device__ float g_Xf [2][OUTF * OUTF];
__device__ float g_Atb[BATCH * OUTF];          // also reused as fp32 Newton scratch T
__device__ float g_u  [BATCH * OUTF];
__device__ float g_z  [BATCH * OUTF];
__device__ bf16 g_Wh [OUTF * INF],  g_Wl [OUTF * INF];
__device__ bf16 g_Wth[INF * OUTF],  g_Wtl[INF * OUTF];
__device__ bf16 g_xh [BATCH * INF], g_xl [BATCH * INF];
__device__ bf16 g_Mh [OUTF * OUTF], g_Ml [OUTF * OUTF];
__device__ bf16 g_Xh [2][OUTF * OUTF], g_Xl [2][OUTF * OUTF];
__device__ bf16 g_Th [OUTF * OUTF], g_Tl [OUTF * OUTF];
__device__ bf16 g_rh [2][BATCH * OUTF], g_rl [2][BATCH * OUTF];
__device__ unsigned int g_snorm;

// ---------------- helpers ----------------
// k-pair permutation within each 32-element block:
// s -> 16*ks + 4*t + 2*r + o   (ks=s/16, w=s%16, r=w/8, q=w%8, t=q/2, o=q%2)
// Result layout: [0,1,8,9, 2,3,10,11, 4,5,12,13, 6,7,14,15, 16,17,24,25, ...]
// so a lane's mma pair {kk,kk+1} and {kk+8,kk+9} are one contiguous u64.
__device__ __forceinline__ size_t kperm(size_t idx) {
    unsigned s = (unsigned)idx & 31u;
    unsigned p = ((s >> 4) << 4) + (((s & 7u) >> 1) << 2) + (((s & 15u) >> 3) << 1) + (s & 1u);
    return (idx & ~(size_t)31) + p;
}

__device__ __forceinline__ uint32_t smem_u32_of(const void* p) {
    uint32_t a;
    asm("{ .reg .u64 t; cvta.to.shared.u64 t, %1; cvt.u32.u64 %0, t; }" : "=r"(a) : "l"(p));
    return a;
}
__device__ __forceinline__ void cp16(uint32_t saddr, const void* g) {
    asm volatile("cp.async.cg.shared.global [%0], [%1], 16;" :: "r"(saddr), "l"(g));
}
#define CP_COMMIT() asm volatile("cp.async.commit_group;" ::: "memory")
#define CP_WAIT0()  asm volatile("cp.async.wait_group 0;" ::: "memory")

__device__ __forceinline__ void mma16816(float* c, const uint32_t* a, uint32_t b0, uint32_t b1) {
    asm volatile("mma.sync.aligned.m16n8k16.row.col.f32.bf16.bf16.f32 "
        "{%0,%1,%2,%3}, {%4,%5,%6,%7}, {%8,%9}, {%0,%1,%2,%3};"
        : "+f"(c[0]), "+f"(c[1]), "+f"(c[2]), "+f"(c[3])
        : "r"(a[0]), "r"(a[1]), "r"(a[2]), "r"(a[3]), "r"(b0), "r"(b1));
}
// writes pair (col even) into PERMUTED split buffers
__device__ __forceinline__ void split_store2(bf16* H, bf16* L, size_t idx, float v0, float v1) {
    size_t dst = kperm(idx);           // o=0,1 stay contiguous
    bf16 h0 = __float2bfloat16_rn(v0), h1 = __float2bfloat16_rn(v1);
    bf16 l0 = __float2bfloat16_rn(v0 - __bfloat162float(h0));
    bf16 l1 = __float2bfloat16_rn(v1 - __bfloat162float(h1));
    *(uint32_t*)(H + dst) = (uint32_t)__bfloat16_as_ushort(h0) | ((uint32_t)__bfloat16_as_ushort(h1) << 16);
    *(uint32_t*)(L + dst) = (uint32_t)__bfloat16_as_ushort(l0) | ((uint32_t)__bfloat16_as_ushort(l1) << 16);
}

// ------------- bf16x3 HMMA GEMM: C[m][n] = sum_k A[m][k]*B[n][k] (NT) -------------
// CTA 128x128, BK=32, cp.async double buffer. Split operands stored k-permuted
// (see kperm) -> each fragment pair is ONE LDS.64 (48 per warp-chunk vs 128 LDS.32).
// Row stride RS=48 elems (24 words): u64 half-warp phase puts the four g-blocks
// at word offsets {0,24,16,8} mod 32 -> all 32 banks exactly once -> conflict-free.
// (RS=40 in R11 aliased blocks at 0/28 -> 2-way conflict -> regression.)
#define RS 48                          // smem row stride in elements (96B)
#define TILE_E (128 * RS)              // 6144 elements per tile
#define TILE_B2 (TILE_E * 2)           // tile bytes (12288)
#define STAGE_E (4 * TILE_E)           // Ah,Al,Bh,Bl per stage
#define STAGE_B2 (STAGE_E * 2)         // stage bytes (49152)
#define GEMM_SMEM_B (2 * STAGE_B2)     // 98304 bytes

template <int EPI>
__global__ __launch_bounds__(256, 2)
void gemm_mma(const bf16* __restrict__ Ah, const bf16* __restrict__ Al,
              const bf16* __restrict__ Bh, const bf16* __restrict__ Bl,
              int Kd, int Nd, float alpha, float beta,
              const float* __restrict__ Dm, float diag,
              float* __restrict__ Cf, bf16* __restrict__ Chi, bf16* __restrict__ Clo,
              const float* __restrict__ Atb, float* __restrict__ Uio,
              float* __restrict__ Z, bf16* __restrict__ Rh, bf16* __restrict__ Rl) {
    extern __shared__ bf16 sm[];   // [2][4][128*RS]
    const uint32_t sb = smem_u32_of(sm);

    const int tid = threadIdx.x, wid = tid >> 5, lane = tid & 31;
    const int m0 = blockIdx.y * 128, n0 = blockIdx.x * 128;
    const int wm = wid & 3, wn = wid >> 2;       // warp tile 32x64 at (wm*32, wn*64)
    const int g = lane >> 2, t = lane & 3;       // PTX fragment lane decomposition

    // loader mapping: row = tid/2 for all four tiles; (tid&1) selects k-half
    const int lr = tid >> 1;
    const int cc = (tid & 1) * 2;                // uint4 chunk index {0,2}
    const bf16* gAh = Ah + (size_t)(m0 + lr) * Kd;
    const bf16* gAl = Al + (size_t)(m0 + lr) * Kd;
    const bf16* gBh = Bh + (size_t)(n0 + lr) * Kd;
    const bf16* gBl = Bl + (size_t)(n0 + lr) * Kd;
    const uint32_t so0b = (uint32_t)(lr * RS + cc * 8) * 2;        // byte offsets (16B aligned)
    const uint32_t so1b = (uint32_t)(lr * RS + (cc + 1) * 8) * 2;

#define CP_LOAD(stg_, kt_) do { \
    const int _ko = (kt_) << 5; \
    const uint32_t _s = sb + (stg_) * STAGE_B2; \
    cp16(_s + so0b,                gAh + _ko + cc * 8); \
    cp16(_s + so1b,                gAh + _ko + (cc + 1) * 8); \
    cp16(_s + TILE_B2 + so0b,      gAl + _ko + cc * 8); \
    cp16(_s + TILE_B2 + so1b,      gAl + _ko + (cc + 1) * 8); \
    cp16(_s + 2 * TILE_B2 + so0b,  gBh + _ko + cc * 8); \
    cp16(_s + 2 * TILE_B2 + so1b,  gBh + _ko + (cc + 1) * 8); \
    cp16(_s + 3 * TILE_B2 + so0b,  gBl + _ko + cc * 8); \
    cp16(_s + 3 * TILE_B2 + so1b,  gBl + _ko + (cc + 1) * 8); \
} while (0)

    float acc[2][8][4];
#pragma unroll
    for (int i = 0; i < 2; i++)
#pragma unroll
        for (int j = 0; j < 8; j++)
#pragma unroll
            for (int e = 0; e < 4; e++) acc[i][j][e] = 0.f;

    const int nk = Kd >> 5;

    CP_LOAD(0, 0);
    CP_COMMIT();

    for (int kt = 0; kt < nk; kt++) {
        const int cb = kt & 1;
        CP_WAIT0();          // chunk kt landed (only group in flight)
        __syncthreads();     // data visible; all warps done reading stage cb^1
        if (kt + 1 < nk) {
            CP_LOAD(cb ^ 1, kt + 1);
            CP_COMMIT();
        }

        const bf16* sAh = sm + cb * STAGE_E;
        const bf16* sAl = sAh + TILE_E;
        const bf16* sBh = sAh + 2 * TILE_E;
        const bf16* sBl = sAh + 3 * TILE_E;

#pragma unroll
        for (int ks = 0; ks < 2; ks++) {
            const int fo = ks * 16 + t * 4;      // permuted u64 group offset (elements)
            uint32_t ahf[2][4], alf[2][4];
#pragma unroll
            for (int mf = 0; mf < 2; mf++) {
                int r0i = (wm * 32 + mf * 16 + g) * RS + fo;
                int r1i = r0i + 8 * RS;
                uint2 h0 = *(const uint2*)&sAh[r0i];   // {a0, a2} of hi
                uint2 h1 = *(const uint2*)&sAh[r1i];   // {a1, a3} of hi
                uint2 l0 = *(const uint2*)&sAl[r0i];
                uint2 l1 = *(const uint2*)&sAl[r1i];
                ahf[mf][0] = h0.x; ahf[mf][1] = h1.x; ahf[mf][2] = h0.y; ahf[mf][3] = h1.y;
                alf[mf][0] = l0.x; alf[mf][1] = l1.x; alf[mf][2] = l0.y; alf[mf][3] = l1.y;
            }
#pragma unroll
            for (int nn = 0; nn < 8; nn++) {
                int bi = (wn * 64 + nn * 8 + g) * RS + fo;
                uint2 bh = *(const uint2*)&sBh[bi];    // {b0, b1} of hi
                uint2 bl = *(const uint2*)&sBl[bi];
#pragma unroll
                for (int mf = 0; mf < 2; mf++) {
                    float* c = acc[mf][nn];
                    mma16816(c, ahf[mf], bh.x, bh.y);
                    mma16816(c, ahf[mf], bl.x, bl.y);
                    mma16816(c, alf[mf], bh.x, bh.y);
                }
            }
        }
    }

    // ---- epilogue (PTX D-fragment table: row = g + ro*8, col = 2t) ----
#pragma unroll
    for (int mf = 0; mf < 2; mf++) {
#pragma unroll
        for (int nf = 0; nf < 8; nf++) {
            const float* c = acc[mf][nf];
#pragma unroll
            for (int ro = 0; ro < 2; ro++) {
                int r = m0 + wm * 32 + mf * 16 + g + ro * 8;
                int col = n0 + wn * 64 + nf * 8 + t * 2;
                size_t idx = (size_t)r * Nd + col;
                float v0 = c[2 * ro], v1 = c[2 * ro + 1];
                if (EPI == 0) {
                    v0 *= alpha; v1 *= alpha;
                    if (Dm) {
                        float2 d2 = *(const float2*)(Dm + idx);
                        v0 = fmaf(beta, d2.x, v0);
                        v1 = fmaf(beta, d2.y, v1);
                    }
                    if (diag != 0.f) {
                        if (r == col) v0 += diag;
                        if (r == col + 1) v1 += diag;
                    }
                    if (Cf) *(float2*)(Cf + idx) = make_float2(v0, v1);
                    if (Chi) split_store2(Chi, Clo, idx, v0, v1);
                } else {
                    float2 u2 = *(const float2*)(Uio + idx);
                    float2 a2 = *(const float2*)(Atb + idx);
                    float zu0 = v0 + u2.x, zu1 = v1 + u2.y;
                    float az0 = fabsf(zu0) - LAMBDA, az1 = fabsf(zu1) - LAMBDA;
                    float z0 = (az0 > 0.f) ? copysignf(az0, zu0) : 0.f;
                    float z1 = (az1 > 0.f) ? copysignf(az1, zu1) : 0.f;
                    *(float2*)(Z + idx) = make_float2(z0, z1);
                    *(float2*)(Uio + idx) = make_float2(zu0 - z0, zu1 - z1);
                    split_store2(Rh, Rl, idx, a2.x + 2.f * z0 - zu0, a2.y + 2.f * z1 - zu1);
                }
            }
        }
    }
#undef CP_LOAD
}

// ---------------- proven scalar fp32 SGEMM (from R1), NN form ----------------
__global__ __launch_bounds__(256, 2)
void sgemm_nn(const float* __restrict__ A0, const float* __restrict__ B,
              const float* __restrict__ D, float* __restrict__ Cout,
              int Md, int Nd, int Kd, float alpha, float beta) {
    constexpr int BM = 128, BN = 128, BK = 16;
    __shared__ float As[BK][BM];
    __shared__ float Bs[BK][BN];
    const int tid = threadIdx.x;
    const int row0 = blockIdx.y * BM;
    const int col0 = blockIdx.x * BN;
    const int tx = tid & 15;
    const int ty = tid >> 4;
    const int aRow = tid >> 1;
    const int aSeg = (tid & 1) * 8;

    float acc[8][8];
#pragma unroll
    for (int i = 0; i < 8; i++)
#pragma unroll
        for (int j = 0; j < 8; j++) acc[i][j] = 0.f;

    for (int k0 = 0; k0 < Kd; k0 += BK) {
#pragma unroll
        for (int h = 0; h < 2; h++) {
            int kc = aSeg + h * 4;
            int gidx = (row0 + aRow) * Kd + k0 + kc;
            float4 va = *(const float4*)(A0 + gidx);
            As[kc + 0][aRow] = va.x;
            As[kc + 1][aRow] = va.y;
            As[kc + 2][aRow] = va.z;
            As[kc + 3][aRow] = va.w;
        }
#pragma unroll
        for (int h = 0; h < 2; h++) {
            int v = tid * 2 + h;
            int br = v >> 5;
            int bc = (v & 31) * 4;
            float4 vb = *(const float4*)(B + (k0 + br) * Nd + col0 + bc);
            *(float4*)(&Bs[br][bc]) = vb;
        }
        __syncthreads();
#pragma unroll
        for (int kk = 0; kk < BK; kk++) {
            float ra[8], rb[8];
            *(float4*)(ra)     = *(const float4*)(&As[kk][ty * 8]);
            *(float4*)(ra + 4) = *(const float4*)(&As[kk][ty * 8 + 4]);
            *(float4*)(rb)     = *(const float4*)(&Bs[kk][tx * 8]);
            *(float4*)(rb + 4) = *(const float4*)(&Bs[kk][tx * 8 + 4]);
#pragma unroll
            for (int i = 0; i < 8; i++)
#pragma unroll
                for (int j = 0; j < 8; j++) acc[i][j] = fmaf(ra[i], rb[j], acc[i][j]);
        }
        __syncthreads();
    }
#pragma unroll
    for (int i = 0; i < 8; i++) {
        int r = row0 + ty * 8 + i;
#pragma unroll
        for (int j = 0; j < 8; j++) {
            int c = col0 + tx * 8 + j;
            int idx = r * Nd + c;
            float v = alpha * acc[i][j];
            if (D != nullptr) v = fmaf(beta, D[idx], v);
            Cout[idx] = v;
        }
    }
}

// ---------------- helpers ----------------
__global__ void reset_scalar_kernel() { g_snorm = 0u; }

__global__ void row_abs_sum_max_kernel() {
    __shared__ float sh[256];
    int row = blockIdx.x;
    float s = 0.f;
    for (int c = threadIdx.x; c < OUTF; c += 256) s += fabsf(g_Mf[row * OUTF + c]);
    sh[threadIdx.x] = s; __syncthreads();
    for (int o = 128; o > 0; o >>= 1) { if (threadIdx.x < o) sh[threadIdx.x] += sh[threadIdx.x + o]; __syncthreads(); }
    if (threadIdx.x == 0) atomicMax(&g_snorm, __float_as_uint(sh[0]));
}

__global__ void init_X_kernel() {
    int idx = blockIdx.x * blockDim.x + threadIdx.x;
    int r = idx >> 11, c = idx & (OUTF - 1);
    float s = __uint_as_float(g_snorm);
    float v = (r == c) ? 2.0f / (s + 1.0f) : 0.0f;
    g_Xf[0][idx] = v;
    bf16 h = __float2bfloat16_rn(v);
    size_t dst = kperm((size_t)idx);
    g_Xh[0][dst] = h;
    g_Xl[0][dst] = __float2bfloat16_rn(v - __bfloat162float(h));
}

__global__ void zero_u_kernel() {
    int idx = blockIdx.x * blockDim.x + threadIdx.x;
    ((float4*)g_u)[idx] = make_float4(0.f, 0.f, 0.f, 0.f);
}

__global__ void convert_split_kernel(const float* __restrict__ src, bf16* __restrict__ hi, bf16* __restrict__ lo) {
    int idx = blockIdx.x * blockDim.x + threadIdx.x;
    float v = src[idx];
    bf16 h = __float2bfloat16_rn(v);
    size_t dst = kperm((size_t)idx);
    hi[dst] = h;
    lo[dst] = __float2bfloat16_rn(v - __bfloat162float(h));
}

__global__ void transpose_convert_kernel(const float* __restrict__ W) {
    __shared__ float tile[32][33];
    int tx = threadIdx.x, ty = threadIdx.y;
    int r0 = blockIdx.y * 32, c0 = blockIdx.x * 32;
#pragma unroll
    for (int i = 0; i < 4; i++)
        tile[ty + i * 8][tx] = W[(size_t)(r0 + ty + i * 8) * INF + c0 + tx];
    __syncthreads();
#pragma unroll
    for (int i = 0; i < 4; i++) {
        float v = tile[tx][ty + i * 8];
        size_t o = kperm((size_t)(c0 + ty + i * 8) * OUTF + r0 + tx);
        bf16 h = __float2bfloat16_rn(v);
        g_Wth[o] = h;
        g_Wtl[o] = __float2bfloat16_rn(v - __bfloat162float(h));
    }
}

// ---------------- host ----------------
extern "C" void kernel_launch(void* const* d_in, const int* in_sizes, int n_in,
                              void* d_out, int out_size) {
    (void)in_sizes; (void)n_in; (void)out_size;
    const float* x = (const float*)d_in[0];
    const float* W = (const float*)d_in[1];
    float* out = (float*)d_out;

    float *Mf, *Xf0, *Xf1, *Atb, *u, *z;
    bf16 *Wh, *Wl, *Wth, *Wtl, *xh, *xl, *Mh, *Ml, *Th, *Tl;
    bf16 *Xh0, *Xl0, *Xh1, *Xl1, *rh0, *rl0, *rh1, *rl1;
    cudaGetSymbolAddress((void**)&Mf, g_Mf);
    cudaGetSymbolAddress((void**)&Xf0, g_Xf);   Xf1 = Xf0 + OUTF * OUTF;
    cudaGetSymbolAddress((void**)&Atb, g_Atb);
    cudaGetSymbolAddress((void**)&u, g_u);
    cudaGetSymbolAddress((void**)&z, g_z);
    cudaGetSymbolAddress((void**)&Wh, g_Wh);  cudaGetSymbolAddress((void**)&Wl, g_Wl);
    cudaGetSymbolAddress((void**)&Wth, g_Wth); cudaGetSymbolAddress((void**)&Wtl, g_Wtl);
    cudaGetSymbolAddress((void**)&xh, g_xh);  cudaGetSymbolAddress((void**)&xl, g_xl);
    cudaGetSymbolAddress((void**)&Mh, g_Mh);  cudaGetSymbolAddress((void**)&Ml, g_Ml);
    cudaGetSymbolAddress((void**)&Th, g_Th);  cudaGetSymbolAddress((void**)&Tl, g_Tl);
    cudaGetSymbolAddress((void**)&Xh0, g_Xh); Xh1 = Xh0 + OUTF * OUTF;
    cudaGetSymbolAddress((void**)&Xl0, g_Xl); Xl1 = Xl0 + OUTF * OUTF;
    cudaGetSymbolAddress((void**)&rh0, g_rh); rh1 = rh0 + BATCH * OUTF;
    cudaGetSymbolAddress((void**)&rl0, g_rl); rl1 = rl0 + BATCH * OUTF;

    cudaFuncSetAttribute(gemm_mma<0>, cudaFuncAttributeMaxDynamicSharedMemorySize, GEMM_SMEM_B);
    cudaFuncSetAttribute(gemm_mma<1>, cudaFuncAttributeMaxDynamicSharedMemorySize, GEMM_SMEM_B);

    dim3 blk(256);
    dim3 g_oo(OUTF / 128, OUTF / 128);
    dim3 g_bo(OUTF / 128, BATCH / 128);
    dim3 g_bi(INF / 128, BATCH / 128);

    convert_split_kernel<<<OUTF * INF / 256, 256>>>(W, Wh, Wl);
    convert_split_kernel<<<BATCH * INF / 256, 256>>>(x, xh, xl);
    transpose_convert_kernel<<<dim3(INF / 32, OUTF / 32), dim3(32, 8)>>>(W);
    reset_scalar_kernel<<<1, 1>>>();
    zero_u_kernel<<<BATCH * OUTF / 1024, 256>>>();

    // M = W W^T + I  (fp32 + split)
    gemm_mma<0><<<g_oo, blk, GEMM_SMEM_B>>>(Wh, Wl, Wh, Wl, INF, OUTF, 1.f, 0.f,
        nullptr, 1.f, Mf, Mh, Ml, nullptr, nullptr, nullptr, nullptr, nullptr);
    row_abs_sum_max_kernel<<<OUTF, 256>>>();
    init_X_kernel<<<OUTF * OUTF / 256, 256>>>();

    // Newton-Schulz (MMA): X <- 2X - X(MX)
    int cur = 0;
    for (int it = 0; it < NEWTON_MMA_ITERS; it++) {
        bf16* Xh = cur ? Xh1 : Xh0; bf16* Xl = cur ? Xl1 : Xl0;
        float* Xc = cur ? Xf1 : Xf0;
        int nxt = 1 - cur;
        gemm_mma<0><<<g_oo, blk, GEMM_SMEM_B>>>(Mh, Ml, Xh, Xl, OUTF, OUTF, 1.f, 0.f,
            nullptr, 0.f, nullptr, Th, Tl, nullptr, nullptr, nullptr, nullptr, nullptr);
        gemm_mma<0><<<g_oo, blk, GEMM_SMEM_B>>>(Xh, Xl, Th, Tl, OUTF, OUTF, -1.f, 2.f,
            Xc, 0.f, nxt ? Xf1 : Xf0, nxt ? Xh1 : Xh0, nxt ? Xl1 : Xl0,
            nullptr, nullptr, nullptr, nullptr, nullptr);
        cur = nxt;
    }

    // fp32 scalar refinement (proven kernel): pins Minv to fp32 floor.
    for (int it = 0; it < NEWTON_F32_ITERS; it++) {
        float* Xc = cur ? Xf1 : Xf0;
        float* Xo = cur ? Xf0 : Xf1;
        sgemm_nn<<<g_oo, blk>>>(Mf, Xc, nullptr, Atb, OUTF, OUTF, OUTF, 1.f, 0.f);
        sgemm_nn<<<g_oo, blk>>>(Xc, Atb, Xc, Xo, OUTF, OUTF, OUTF, -1.f, 2.f);
        cur = 1 - cur;
    }
    convert_split_kernel<<<OUTF * OUTF / 256, 256>>>(cur ? Xf1 : Xf0, Th, Tl);

    // Atb = x W^T (fp32) ; r0 = Atb (split)
    gemm_mma<0><<<g_bo, blk, GEMM_SMEM_B>>>(xh, xl, Wh, Wl, INF, OUTF, 1.f, 0.f,
        nullptr, 0.f, Atb, rh0, rl0, nullptr, nullptr, nullptr, nullptr, nullptr);

    // ADMM iterations (fully fused), Minv = Th/Tl
    int ib = 0;
    for (int it = 0; it < ADMM_ITERS; it++) {
        gemm_mma<1><<<g_bo, blk, GEMM_SMEM_B>>>(
            ib ? rh1 : rh0, ib ? rl1 : rl0, Th, Tl, OUTF, OUTF, 1.f, 0.f,
            nullptr, 0.f, nullptr, nullptr, nullptr,
            Atb, u, z, ib ? rh0 : rh1, ib ? rl0 : rl1);
        ib = 1 - ib;
    }

    // encoded = z ; decoded = z @ W  (z splits overwrite Th/Tl, Minv dead now)
    cudaMemcpyAsync(out, z, (size_t)BATCH * OUTF * sizeof(float), cudaMemcpyDeviceToDevice, 0);
    convert_split_kernel<<<BATCH * OUTF / 256, 256>>>(z, Th, Tl);
    gemm_mma<0><<<g_bi, blk, GEMM_SMEM_B>>>(Th, Tl, Wth, Wtl, OUTF, INF, 1.f, 0.f,
        nullptr, 0.f, out + (size_t)BATCH * OUTF, nullptr, nullptr,
        nullptr, nullptr, nullptr, nullptr, nullptr);
}

// round 15
// speedup vs baseline: 1.2318x; 1.2318x over previous
#include <cuda_runtime.h>
#include <cuda_bf16.h>
#include <stdint.h>
#include <math.h>
#include <stddef.h>

#define BATCH 2048
#define INF   1024
#define OUTF  2048
#define LAMBDA 0.2f
#define ADMM_ITERS 100
#define NEWTON_MMA_ITERS 8
#define NEWTON_F32_ITERS 1
typedef __nv_bfloat16 bf16;

// ---------------- scratch ----------------
__device__ float g_Mf [OUTF * OUTF];
__device__ float g_Xf [2][OUTF * OUTF];
__device__ float g_Atb[BATCH * OUTF];          // also reused as fp32 Newton scratch T
__device__ float g_u  [BATCH * OUTF];
__device__ float g_z  [BATCH * OUTF];
__device__ bf16 g_Wh [OUTF * INF],  g_Wl [OUTF * INF];
__device__ bf16 g_Wth[INF * OUTF],  g_Wtl[INF * OUTF];
__device__ bf16 g_xh [BATCH * INF], g_xl [BATCH * INF];
__device__ bf16 g_Mh [OUTF * OUTF], g_Ml [OUTF * OUTF];
__device__ bf16 g_Xh [2][OUTF * OUTF], g_Xl [2][OUTF * OUTF];
__device__ bf16 g_Th [OUTF * OUTF], g_Tl [OUTF * OUTF];
__device__ bf16 g_rh [2][BATCH * OUTF], g_rl [2][BATCH * OUTF];
__device__ unsigned int g_snorm;

// ---------------- helpers ----------------
__device__ __forceinline__ uint32_t smem_u32_of(const void* p) {
    uint32_t a;
    asm("{ .reg .u64 t; cvta.to.shared.u64 t, %1; cvt.u32.u64 %0, t; }" : "=r"(a) : "l"(p));
    return a;
}
__device__ __forceinline__ void cp16(uint32_t saddr, const void* g) {
    asm volatile("cp.async.cg.shared.global [%0], [%1], 16;" :: "r"(saddr), "l"(g));
}
#define CP_COMMIT() asm volatile("cp.async.commit_group;" ::: "memory")
#define CP_WAIT0()  asm volatile("cp.async.wait_group 0;" ::: "memory")

__device__ __forceinline__ void mma16816(float* c, const uint32_t* a, uint32_t b0, uint32_t b1) {
    asm volatile("mma.sync.aligned.m16n8k16.row.col.f32.bf16.bf16.f32 "
        "{%0,%1,%2,%3}, {%4,%5,%6,%7}, {%8,%9}, {%0,%1,%2,%3};"
        : "+f"(c[0]), "+f"(c[1]), "+f"(c[2]), "+f"(c[3])
        : "r"(a[0]), "r"(a[1]), "r"(a[2]), "r"(a[3]), "r"(b0), "r"(b1));
}
__device__ __forceinline__ void split_store2(bf16* H, bf16* L, size_t idx, float v0, float v1) {
    bf16 h0 = __float2bfloat16_rn(v0), h1 = __float2bfloat16_rn(v1);
    bf16 l0 = __float2bfloat16_rn(v0 - __bfloat162float(h0));
    bf16 l1 = __float2bfloat16_rn(v1 - __bfloat162float(h1));
    *(uint32_t*)(H + idx) = (uint32_t)__bfloat16_as_ushort(h0) | ((uint32_t)__bfloat16_as_ushort(h1) << 16);
    *(uint32_t*)(L + idx) = (uint32_t)__bfloat16_as_ushort(l0) | ((uint32_t)__bfloat16_as_ushort(l1) << 16);
}

// ------------- bf16x3 HMMA GEMM: C[m][n] = sum_k A[m][k]*B[n][k] (NT) -------------
// CTA 128x128, BK=32, cp.async double buffer (R10 engine — best measured:
// ~93% of legacy-HMMA roofline; LDS-layout variants regressed, do not revisit).
#define RS 40                          // smem row stride in elements
#define TILE_E (128 * RS)              // 5120 elements per tile
#define TILE_B2 (TILE_E * 2)           // tile bytes (10240)
#define STAGE_E (4 * TILE_E)           // Ah,Al,Bh,Bl per stage
#define STAGE_B2 (STAGE_E * 2)         // stage bytes (40960)
#define GEMM_SMEM_B (2 * STAGE_B2)     // 81920 bytes

template <int EPI>
__global__ __launch_bounds__(256, 2)
void gemm_mma(const bf16* __restrict__ Ah, const bf16* __restrict__ Al,
              const bf16* __restrict__ Bh, const bf16* __restrict__ Bl,
              int Kd, int Nd, float alpha, float beta,
              const float* __restrict__ Dm, float diag,
              float* __restrict__ Cf, bf16* __restrict__ Chi, bf16* __restrict__ Clo,
              const float* __restrict__ Atb, float* __restrict__ Uio,
              float* __restrict__ Z, bf16* __restrict__ Rh, bf16* __restrict__ Rl) {
    extern __shared__ bf16 sm[];   // [2][4][128*RS]
    const uint32_t sb = smem_u32_of(sm);

    const int tid = threadIdx.x, wid = tid >> 5, lane = tid & 31;
    const int m0 = blockIdx.y * 128, n0 = blockIdx.x * 128;
    const int wm = wid & 3, wn = wid >> 2;       // warp tile 32x64 at (wm*32, wn*64)
    const int g = lane >> 2, t = lane & 3;       // PTX fragment lane decomposition

    // loader mapping: row = tid/2 for all four tiles; (tid&1) selects k-half
    const int lr = tid >> 1;
    const int cc = (tid & 1) * 2;                // uint4 chunk index {0,2}
    const bf16* gAh = Ah + (size_t)(m0 + lr) * Kd;
    const bf16* gAl = Al + (size_t)(m0 + lr) * Kd;
    const bf16* gBh = Bh + (size_t)(n0 + lr) * Kd;
    const bf16* gBl = Bl + (size_t)(n0 + lr) * Kd;
    const uint32_t so0b = (uint32_t)(lr * RS + cc * 8) * 2;        // byte offsets (16B aligned)
    const uint32_t so1b = (uint32_t)(lr * RS + (cc + 1) * 8) * 2;

#define CP_LOAD(stg_, kt_) do { \
    const int _ko = (kt_) << 5; \
    const uint32_t _s = sb + (stg_) * STAGE_B2; \
    cp16(_s + so0b,                gAh + _ko + cc * 8); \
    cp16(_s + so1b,                gAh + _ko + (cc + 1) * 8); \
    cp16(_s + TILE_B2 + so0b,      gAl + _ko + cc * 8); \
    cp16(_s + TILE_B2 + so1b,      gAl + _ko + (cc + 1) * 8); \
    cp16(_s + 2 * TILE_B2 + so0b,  gBh + _ko + cc * 8); \
    cp16(_s + 2 * TILE_B2 + so1b,  gBh + _ko + (cc + 1) * 8); \
    cp16(_s + 3 * TILE_B2 + so0b,  gBl + _ko + cc * 8); \
    cp16(_s + 3 * TILE_B2 + so1b,  gBl + _ko + (cc + 1) * 8); \
} while (0)

    float acc[2][8][4];
#pragma unroll
    for (int i = 0; i < 2; i++)
#pragma unroll
        for (int j = 0; j < 8; j++)
#pragma unroll
            for (int e = 0; e < 4; e++) acc[i][j][e] = 0.f;

    const int nk = Kd >> 5;

    CP_LOAD(0, 0);
    CP_COMMIT();

    for (int kt = 0; kt < nk; kt++) {
        const int cb = kt & 1;
        CP_WAIT0();          // chunk kt landed (only group in flight)
        __syncthreads();     // data visible; all warps done reading stage cb^1
        if (kt + 1 < nk) {
            CP_LOAD(cb ^ 1, kt + 1);
            CP_COMMIT();
        }

        const bf16* sAh = sm + cb * STAGE_E;
        const bf16* sAl = sAh + TILE_E;
        const bf16* sBh = sAh + 2 * TILE_E;
        const bf16* sBl = sAh + 3 * TILE_E;

#pragma unroll
        for (int ks = 0; ks < 2; ks++) {
            const int kk = ks * 16 + 2 * t;      // element offset of this lane's k-pair
            uint32_t ahf[2][4], alf[2][4];
#pragma unroll
            for (int mf = 0; mf < 2; mf++) {
                int r0i = (wm * 32 + mf * 16 + g) * RS + kk;
                int r1i = r0i + 8 * RS;
                ahf[mf][0] = *(const uint32_t*)&sAh[r0i];
                ahf[mf][1] = *(const uint32_t*)&sAh[r1i];
                ahf[mf][2] = *(const uint32_t*)&sAh[r0i + 8];
                ahf[mf][3] = *(const uint32_t*)&sAh[r1i + 8];
                alf[mf][0] = *(const uint32_t*)&sAl[r0i];
                alf[mf][1] = *(const uint32_t*)&sAl[r1i];
                alf[mf][2] = *(const uint32_t*)&sAl[r0i + 8];
                alf[mf][3] = *(const uint32_t*)&sAl[r1i + 8];
            }
#pragma unroll
            for (int nn = 0; nn < 8; nn++) {
                int bi = (wn * 64 + nn * 8 + g) * RS + kk;
                uint32_t bh0 = *(const uint32_t*)&sBh[bi];
                uint32_t bh1 = *(const uint32_t*)&sBh[bi + 8];
                uint32_t bl0 = *(const uint32_t*)&sBl[bi];
                uint32_t bl1 = *(const uint32_t*)&sBl[bi + 8];
#pragma unroll
                for (int mf = 0; mf < 2; mf++) {
                    float* c = acc[mf][nn];
                    mma16816(c, ahf[mf], bh0, bh1);
                    mma16816(c, ahf[mf], bl0, bl1);
                    mma16816(c, alf[mf], bh0, bh1);
                }
            }
        }
    }

    // ---- epilogue (PTX D-fragment table: row = g + ro*8, col = 2t) ----
#pragma unroll
    for (int mf = 0; mf < 2; mf++) {
#pragma unroll
        for (int nf = 0; nf < 8; nf++) {
            const float* c = acc[mf][nf];
#pragma unroll
            for (int ro = 0; ro < 2; ro++) {
                int r = m0 + wm * 32 + mf * 16 + g + ro * 8;
                int col = n0 + wn * 64 + nf * 8 + t * 2;
                size_t idx = (size_t)r * Nd + col;
                float v0 = c[2 * ro], v1 = c[2 * ro + 1];
                if (EPI == 0) {
                    v0 *= alpha; v1 *= alpha;
                    if (Dm) {
                        float2 d2 = *(const float2*)(Dm + idx);
                        v0 = fmaf(beta, d2.x, v0);
                        v1 = fmaf(beta, d2.y, v1);
                    }
                    if (diag != 0.f) {
                        if (r == col) v0 += diag;
                        if (r == col + 1) v1 += diag;
                    }
                    if (Cf) *(float2*)(Cf + idx) = make_float2(v0, v1);
                    if (Chi) split_store2(Chi, Clo, idx, v0, v1);
                } else {
                    float2 u2 = *(const float2*)(Uio + idx);
                    float2 a2 = *(const float2*)(Atb + idx);
                    float zu0 = v0 + u2.x, zu1 = v1 + u2.y;
                    float az0 = fabsf(zu0) - LAMBDA, az1 = fabsf(zu1) - LAMBDA;
                    float z0 = (az0 > 0.f) ? copysignf(az0, zu0) : 0.f;
                    float z1 = (az1 > 0.f) ? copysignf(az1, zu1) : 0.f;
                    *(float2*)(Z + idx) = make_float2(z0, z1);
                    *(float2*)(Uio + idx) = make_float2(zu0 - z0, zu1 - z1);
                    split_store2(Rh, Rl, idx, a2.x + 2.f * z0 - zu0, a2.y + 2.f * z1 - zu1);
                }
            }
        }
    }
#undef CP_LOAD
}

// ---------------- proven scalar fp32 SGEMM (from R1), NN form ----------------
__global__ __launch_bounds__(256, 2)
void sgemm_nn(const float* __restrict__ A0, const float* __restrict__ B,
              const float* __restrict__ D, float* __restrict__ Cout,
              int Md, int Nd, int Kd, float alpha, float beta) {
    constexpr int BM = 128, BN = 128, BK = 16;
    __shared__ float As[BK][BM];
    __shared__ float Bs[BK][BN];
    const int tid = threadIdx.x;
    const int row0 = blockIdx.y * BM;
    const int col0 = blockIdx.x * BN;
    const int tx = tid & 15;
    const int ty = tid >> 4;
    const int aRow = tid >> 1;
    const int aSeg = (tid & 1) * 8;

    float acc[8][8];
#pragma unroll
    for (int i = 0; i < 8; i++)
#pragma unroll
        for (int j = 0; j < 8; j++) acc[i][j] = 0.f;

    for (int k0 = 0; k0 < Kd; k0 += BK) {
#pragma unroll
        for (int h = 0; h < 2; h++) {
            int kc = aSeg + h * 4;
            int gidx = (row0 + aRow) * Kd + k0 + kc;
            float4 va = *(const float4*)(A0 + gidx);
            As[kc + 0][aRow] = va.x;
            As[kc + 1][aRow] = va.y;
            As[kc + 2][aRow] = va.z;
            As[kc + 3][aRow] = va.w;
        }
#pragma unroll
        for (int h = 0; h < 2; h++) {
            int v = tid * 2 + h;
            int br = v >> 5;
            int bc = (v & 31) * 4;
            float4 vb = *(const float4*)(B + (k0 + br) * Nd + col0 + bc);
            *(float4*)(&Bs[br][bc]) = vb;
        }
        __syncthreads();
#pragma unroll
        for (int kk = 0; kk < BK; kk++) {
            float ra[8], rb[8];
            *(float4*)(ra)     = *(const float4*)(&As[kk][ty * 8]);
            *(float4*)(ra + 4) = *(const float4*)(&As[kk][ty * 8 + 4]);
            *(float4*)(rb)     = *(const float4*)(&Bs[kk][tx * 8]);
            *(float4*)(rb + 4) = *(const float4*)(&Bs[kk][tx * 8 + 4]);
#pragma unroll
            for (int i = 0; i < 8; i++)
#pragma unroll
                for (int j = 0; j < 8; j++) acc[i][j] = fmaf(ra[i], rb[j], acc[i][j]);
        }
        __syncthreads();
    }
#pragma unroll
    for (int i = 0; i < 8; i++) {
        int r = row0 + ty * 8 + i;
#pragma unroll
        for (int j = 0; j < 8; j++) {
            int c = col0 + tx * 8 + j;
            int idx = r * Nd + c;
            float v = alpha * acc[i][j];
            if (D != nullptr) v = fmaf(beta, D[idx], v);
            Cout[idx] = v;
        }
    }
}

// ---------------- helpers ----------------
__global__ void reset_scalar_kernel() { g_snorm = 0u; }

__global__ void row_abs_sum_max_kernel() {
    __shared__ float sh[256];
    int row = blockIdx.x;
    float s = 0.f;
    for (int c = threadIdx.x; c < OUTF; c += 256) s += fabsf(g_Mf[row * OUTF + c]);
    sh[threadIdx.x] = s; __syncthreads();
    for (int o = 128; o > 0; o >>= 1) { if (threadIdx.x < o) sh[threadIdx.x] += sh[threadIdx.x + o]; __syncthreads(); }
    if (threadIdx.x == 0) atomicMax(&g_snorm, __float_as_uint(sh[0]));
}

__global__ void init_X_kernel() {
    int idx = blockIdx.x * blockDim.x + threadIdx.x;
    int r = idx >> 11, c = idx & (OUTF - 1);
    float s = __uint_as_float(g_snorm);
    float v = (r == c) ? 2.0f / (s + 1.0f) : 0.0f;
    g_Xf[0][idx] = v;
    bf16 h = __float2bfloat16_rn(v);
    g_Xh[0][idx] = h;
    g_Xl[0][idx] = __float2bfloat16_rn(v - __bfloat162float(h));
}

__global__ void zero_u_kernel() {
    int idx = blockIdx.x * blockDim.x + threadIdx.x;
    ((float4*)g_u)[idx] = make_float4(0.f, 0.f, 0.f, 0.f);
}

__global__ void convert_split_kernel(const float* __restrict__ src, bf16* __restrict__ hi, bf16* __restrict__ lo) {
    int idx = blockIdx.x * blockDim.x + threadIdx.x;
    float v = src[idx];
    bf16 h = __float2bfloat16_rn(v);
    hi[idx] = h;
    lo[idx] = __float2bfloat16_rn(v - __bfloat162float(h));
}

__global__ void transpose_convert_kernel(const float* __restrict__ W) {
    __shared__ float tile[32][33];
    int tx = threadIdx.x, ty = threadIdx.y;
    int r0 = blockIdx.y * 32, c0 = blockIdx.x * 32;
#pragma unroll
    for (int i = 0; i < 4; i++)
        tile[ty + i * 8][tx] = W[(size_t)(r0 + ty + i * 8) * INF + c0 + tx];
    __syncthreads();
#pragma unroll
    for (int i = 0; i < 4; i++) {
        float v = tile[tx][ty + i * 8];
        size_t o = (size_t)(c0 + ty + i * 8) * OUTF + r0 + tx;
        bf16 h = __float2bfloat16_rn(v);
        g_Wth[o] = h;
        g_Wtl[o] = __float2bfloat16_rn(v - __bfloat162float(h));
    }
}

// ---------------- host ----------------
extern "C" void kernel_launch(void* const* d_in, const int* in_sizes, int n_in,
                              void* d_out, int out_size) {
    (void)in_sizes; (void)n_in; (void)out_size;
    const float* x = (const float*)d_in[0];
    const float* W = (const float*)d_in[1];
    float* out = (float*)d_out;

    float *Mf, *Xf0, *Xf1, *Atb, *u, *z;
    bf16 *Wh, *Wl, *Wth, *Wtl, *xh, *xl, *Mh, *Ml, *Th, *Tl;
    bf16 *Xh0, *Xl0, *Xh1, *Xl1, *rh0, *rl0, *rh1, *rl1;
    cudaGetSymbolAddress((void**)&Mf, g_Mf);
    cudaGetSymbolAddress((void**)&Xf0, g_Xf);   Xf1 = Xf0 + OUTF * OUTF;
    cudaGetSymbolAddress((void**)&Atb, g_Atb);
    cudaGetSymbolAddress((void**)&u, g_u);
    cudaGetSymbolAddress((void**)&z, g_z);
    cudaGetSymbolAddress((void**)&Wh, g_Wh);  cudaGetSymbolAddress((void**)&Wl, g_Wl);
    cudaGetSymbolAddress((void**)&Wth, g_Wth); cudaGetSymbolAddress((void**)&Wtl, g_Wtl);
    cudaGetSymbolAddress((void**)&xh, g_xh);  cudaGetSymbolAddress((void**)&xl, g_xl);
    cudaGetSymbolAddress((void**)&Mh, g_Mh);  cudaGetSymbolAddress((void**)&Ml, g_Ml);
    cudaGetSymbolAddress((void**)&Th, g_Th);  cudaGetSymbolAddress((void**)&Tl, g_Tl);
    cudaGetSymbolAddress((void**)&Xh0, g_Xh); Xh1 = Xh0 + OUTF * OUTF;
    cudaGetSymbolAddress((void**)&Xl0, g_Xl); Xl1 = Xl0 + OUTF * OUTF;
    cudaGetSymbolAddress((void**)&rh0, g_rh); rh1 = rh0 + BATCH * OUTF;
    cudaGetSymbolAddress((void**)&rl0, g_rl); rl1 = rl0 + BATCH * OUTF;

    cudaFuncSetAttribute(gemm_mma<0>, cudaFuncAttributeMaxDynamicSharedMemorySize, GEMM_SMEM_B);
    cudaFuncSetAttribute(gemm_mma<1>, cudaFuncAttributeMaxDynamicSharedMemorySize, GEMM_SMEM_B);

    dim3 blk(256);
    dim3 g_oo(OUTF / 128, OUTF / 128);
    dim3 g_bo(OUTF / 128, BATCH / 128);
    dim3 g_bi(INF / 128, BATCH / 128);

    convert_split_kernel<<<OUTF * INF / 256, 256>>>(W, Wh, Wl);
    convert_split_kernel<<<BATCH * INF / 256, 256>>>(x, xh, xl);
    transpose_convert_kernel<<<dim3(INF / 32, OUTF / 32), dim3(32, 8)>>>(W);
    reset_scalar_kernel<<<1, 1>>>();
    zero_u_kernel<<<BATCH * OUTF / 1024, 256>>>();

    // M = W W^T + I  (fp32 + split)
    gemm_mma<0><<<g_oo, blk, GEMM_SMEM_B>>>(Wh, Wl, Wh, Wl, INF, OUTF, 1.f, 0.f,
        nullptr, 1.f, Mf, Mh, Ml, nullptr, nullptr, nullptr, nullptr, nullptr);
    row_abs_sum_max_kernel<<<OUTF, 256>>>();
    init_X_kernel<<<OUTF * OUTF / 256, 256>>>();

    // Newton-Schulz (MMA): X <- 2X - X(MX).  8 iters: err ~0.963^256 ≈ 6e-5,
    // then ONE fp32 iteration squares it to ~4e-9 (fp32 floor). 12+2 was overconverged.
    int cur = 0;
    for (int it = 0; it < NEWTON_MMA_ITERS; it++) {
        bf16* Xh = cur ? Xh1 : Xh0; bf16* Xl = cur ? Xl1 : Xl0;
        float* Xc = cur ? Xf1 : Xf0;
        int nxt = 1 - cur;
        gemm_mma<0><<<g_oo, blk, GEMM_SMEM_B>>>(Mh, Ml, Xh, Xl, OUTF, OUTF, 1.f, 0.f,
            nullptr, 0.f, nullptr, Th, Tl, nullptr, nullptr, nullptr, nullptr, nullptr);
        gemm_mma<0><<<g_oo, blk, GEMM_SMEM_B>>>(Xh, Xl, Th, Tl, OUTF, OUTF, -1.f, 2.f,
            Xc, 0.f, nxt ? Xf1 : Xf0, nxt ? Xh1 : Xh0, nxt ? Xl1 : Xl0,
            nullptr, nullptr, nullptr, nullptr, nullptr);
        cur = nxt;
    }

    // fp32 scalar refinement (proven kernel): pins Minv to fp32 floor.
    for (int it = 0; it < NEWTON_F32_ITERS; it++) {
        float* Xc = cur ? Xf1 : Xf0;
        float* Xo = cur ? Xf0 : Xf1;
        sgemm_nn<<<g_oo, blk>>>(Mf, Xc, nullptr, Atb, OUTF, OUTF, OUTF, 1.f, 0.f);
        sgemm_nn<<<g_oo, blk>>>(Xc, Atb, Xc, Xo, OUTF, OUTF, OUTF, -1.f, 2.f);
        cur = 1 - cur;
    }
    convert_split_kernel<<<OUTF * OUTF / 256, 256>>>(cur ? Xf1 : Xf0, Th, Tl);

    // Atb = x W^T (fp32) ; r0 = Atb (split)
    gemm_mma<0><<<g_bo, blk, GEMM_SMEM_B>>>(xh, xl, Wh, Wl, INF, OUTF, 1.f, 0.f,
        nullptr, 0.f, Atb, rh0, rl0, nullptr, nullptr, nullptr, nullptr, nullptr);

    // ADMM iterations (fully fused), Minv = Th/Tl
    int ib = 0;
    for (int it = 0; it < ADMM_ITERS; it++) {
        gemm_mma<1><<<g_bo, blk, GEMM_SMEM_B>>>(
            ib ? rh1 : rh0, ib ? rl1 : rl0, Th, Tl, OUTF, OUTF, 1.f, 0.f,
            nullptr, 0.f, nullptr, nullptr, nullptr,
            Atb, u, z, ib ? rh0 : rh1, ib ? rl0 : rl1);
        ib = 1 - ib;
    }

    // encoded = z ; decoded = z @ W  (z splits overwrite Th/Tl, Minv dead now)
    cudaMemcpyAsync(out, z, (size_t)BATCH * OUTF * sizeof(float), cudaMemcpyDeviceToDevice, 0);
    convert_split_kernel<<<BATCH * OUTF / 256, 256>>>(z, Th, Tl);
    gemm_mma<0><<<g_bi, blk, GEMM_SMEM_B>>>(Th, Tl, Wth, Wtl, OUTF, INF, 1.f, 0.f,
        nullptr, 0.f, out + (size_t)BATCH * OUTF, nullptr, nullptr,
        nullptr, nullptr, nullptr, nullptr, nullptr);
}